// round 4
// baseline (speedup 1.0000x reference)
#include <cuda_runtime.h>
#include <cstdint>

#define FULL 0xffffffffu
#define S 8
#define D 64

__device__ __forceinline__ float finf() { return __int_as_float(0x7f800000); }

__global__ __launch_bounds__(128)
void bwm_kernel(const float* __restrict__ g_m,     // B*S*D
                const float* __restrict__ g_act,   // B*S
                const float* __restrict__ g_gate,  // B*S
                const float* __restrict__ g_thr,   // B*S
                const float* __restrict__ g_rstr,  // B*S
                const float* __restrict__ g_W,     // B*S*S
                const float* __restrict__ g_mcur,  // B*S
                const float* __restrict__ g_inp,   // B*D
                const float* __restrict__ g_gsig,  // B*S
                const float* __restrict__ g_rsig,  // B*S
                const int*   __restrict__ g_dt,    // 1 elem (int or float bits) or null
                float* __restrict__ out,
                int B)
{
    const int tid  = blockIdx.x * blockDim.x + threadIdx.x;
    const int b    = tid >> 3;          // batch index (8 lanes per batch)
    const int lane = threadIdx.x & 31;
    const int li   = lane & 7;          // lane-in-group = slot id this lane "owns" for scalars
    const unsigned gsh = (lane >> 3) * 8;  // group bit-shift for ballots
    if (b >= B) return;                 // grid exact for B*8 % 128 == 0; no partial warps

    // ---- dt decode (int 1 or float 1.0, or absent) ----
    float dt = 1.0f;
    if (g_dt) {
        int ib = *g_dt;
        float f = __int_as_float(ib);
        dt = (fabsf(f) > 1e-30f && fabsf(f) < 1e30f) ? f : (float)ib;
    }

    // ---- load m (each lane: 8 floats of every slot), decay by 0.95 ----
    const size_t bm = (size_t)b * (S * D);
    const float4* mp = (const float4*)(g_m + bm);
    float m[S][8];
#pragma unroll
    for (int s = 0; s < S; s++) {
        float4 u = mp[s * 16 + li * 2 + 0];
        float4 v = mp[s * 16 + li * 2 + 1];
        m[s][0] = 0.95f * u.x; m[s][1] = 0.95f * u.y; m[s][2] = 0.95f * u.z; m[s][3] = 0.95f * u.w;
        m[s][4] = 0.95f * v.x; m[s][5] = 0.95f * v.y; m[s][6] = 0.95f * v.z; m[s][7] = 0.95f * v.w;
    }

    // ---- per-slot scalars (lane li owns slot li) ----
    const int sidx = b * S + li;
    const float a0   = g_act[sidx];
    const float gate = g_gate[sidx];
    const float thr  = g_thr[sidx];
    const float rstr = g_rstr[sidx];
    const float mcur = g_mcur[sidx];
    const float gsig = g_gsig[sidx];
    const float rsig = g_rsig[sidx];

    // ---- W row (lane li holds W[li][0..7]) ----
    const float4* wp = (const float4*)(g_W + (size_t)b * (S * S) + li * S);
    float4 w0 = wp[0], w1 = wp[1];
    float Wr[8] = {w0.x, w0.y, w0.z, w0.w, w1.x, w1.y, w1.z, w1.w};

    // ---- inputs (lane li holds 8 floats of input vector) ----
    const float4* ip = (const float4*)(g_inp + (size_t)b * D + li * 8);
    float4 i0 = ip[0], i1 = ip[1];
    float inp[8] = {i0.x, i0.y, i0.z, i0.w, i1.x, i1.y, i1.z, i1.w};

    // ---- decayed activity + activation mask ----
    float a = 0.9f * a0;
    unsigned actm = (__ballot_sync(FULL, a > 0.1f) >> gsh) & 0xFFu;

    // ---- target slot selection (uses ORIGINAL activities) ----
    bool avail = a0 < 0.2f;
    unsigned avm = (__ballot_sync(FULL, avail) >> gsh) & 0xFFu;
    float key = avm ? (avail ? a0 : finf()) : a0;
    float bv = key; int bi = li;
#pragma unroll
    for (int o = 1; o < 8; o <<= 1) {
        float ov = __shfl_xor_sync(FULL, bv, o);
        int   oi = __shfl_xor_sync(FULL, bi, o);
        if (ov < bv || (ov == bv && oi < bi)) { bv = ov; bi = oi; }
    }
    const int ts = bi;  // uniform within group

    // ---- initial squared norms of all 8 slots (all lanes get all 8) ----
    float ns[S];
#pragma unroll
    for (int s = 0; s < S; s++) {
        float p = 0.0f;
#pragma unroll
        for (int k = 0; k < 8; k++) p = fmaf(m[s][k], m[s][k], p);
        ns[s] = p;
    }
#pragma unroll
    for (int o = 1; o < 8; o <<= 1) {
#pragma unroll
        for (int s = 0; s < S; s++) ns[s] += __shfl_xor_sync(FULL, ns[s], o);
    }

    // ---- sequential pairwise interference (exact order i=0..7, j=0..7, j!=i) ----
#pragma unroll
    for (int i = 0; i < S; i++) {
#pragma unroll
        for (int j = 0; j < S; j++) {
            if (j == i) continue;
            float dot = 0.0f;
#pragma unroll
            for (int k = 0; k < 8; k++) dot = fmaf(m[i][k], m[j][k], dot);
            dot += __shfl_xor_sync(FULL, dot, 1);
            dot += __shfl_xor_sync(FULL, dot, 2);
            dot += __shfl_xor_sync(FULL, dot, 4);

            float denom = sqrtf(ns[i]) * sqrtf(ns[j]) + 1e-6f;
            float sim = __fdividef(dot, denom);
            float Wij = __shfl_sync(FULL, Wr[j], i, 8);
            bool cond = ((actm >> i) & 1u) && ((actm >> j) & 1u);
            float sc = cond ? Wij * sim * 0.1f : 0.0f;
#pragma unroll
            for (int k = 0; k < 8; k++) m[i][k] = fmaf(-sc, m[j][k], m[i][k]);
            // ||mi - sc*mj||^2 = ni - 2 sc dot + sc^2 nj  (analytic norm update)
            ns[i] = fmaf(sc * sc, ns[j], fmaf(-2.0f * sc, dot, ns[i]));
        }
    }

    // ---- gating / write ----
    float gl = fmaf(0.3f, fminf(fmaxf(gsig, 0.0f), 1.0f), 0.7f * gate);
    float gs = __shfl_sync(FULL, gl, ts, 8);
    float tv = __shfl_sync(FULL, thr, ts, 8);
    bool wr = gs > tv;

    // input norm (reduced over group)
    float insq = 0.0f;
#pragma unroll
    for (int k = 0; k < 8; k++) insq = fmaf(inp[k], inp[k], insq);
    insq += __shfl_xor_sync(FULL, insq, 1);
    insq += __shfl_xor_sync(FULL, insq, 2);
    insq += __shfl_xor_sync(FULL, insq, 4);
    float innorm = sqrtf(insq);

    float c = wr ? gs * 0.3f : 0.0f;
#pragma unroll
    for (int s = 0; s < S; s++) {
        float cs = (s == ts) ? c : 0.0f;
#pragma unroll
        for (int k = 0; k < 8; k++) {
            // (1-cs)*m + cs*inp ; cs==0 -> exact no-op
            m[s][k] = fmaf(cs, inp[k] - m[s][k], m[s][k]);
        }
    }
    if (wr && li == ts) a = innorm;

    // ---- refresh ----
    float ru = fminf(fmaxf(rsig, 0.0f), 1.0f);
    float rs = (ru > 0.1f) ? rstr * ru : 0.0f;
#pragma unroll
    for (int s = 0; s < S; s++) {
        float f = 1.0f + __shfl_sync(FULL, rs, s, 8);
#pragma unroll
        for (int k = 0; k < 8; k++) m[s][k] *= f;
    }
    a += rs;

    // ---- maintenance current ----
    float mc = (a > 0.1f) ? fmaf(fmaf(0.5f, a, -mcur), 0.1f * dt, mcur)
                          : mcur * 0.95f;

    // ---- capacity-based deactivation ----
    bool active = a > 0.1f;
    unsigned ab = (__ballot_sync(FULL, active) >> gsh) & 0xFFu;
    int ndeact = max(__popc(ab) - 4, 0);
    float mv = active ? a : finf();
    int rank = 0;
#pragma unroll
    for (int s = 0; s < S; s++) {
        float vs = __shfl_sync(FULL, mv, s, 8);
        rank += (vs < mv || (vs == mv && s < li)) ? 1 : 0;
    }
    bool de = active && (rank < ndeact);
    if (de) a *= 0.5f;
    unsigned db = (__ballot_sync(FULL, de) >> gsh) & 0xFFu;
#pragma unroll
    for (int s = 0; s < S; s++) {
        float f = ((db >> s) & 1u) ? 0.7f : 1.0f;
#pragma unroll
        for (int k = 0; k < 8; k++) m[s][k] *= f;
    }

    // ---- scalar outputs ----
    unsigned lb = (__ballot_sync(FULL, a > 0.1f) >> gsh) & 0xFFu;
    int mload = __popc(lb);
    float tot = a, msum = mc;
#pragma unroll
    for (int o = 1; o < 8; o <<= 1) {
        tot  += __shfl_xor_sync(FULL, tot, o);
        msum += __shfl_xor_sync(FULL, msum, o);
    }

    // ---- stores ----
    float4* omp = (float4*)(out + bm);
#pragma unroll
    for (int s = 0; s < S; s++) {
        omp[s * 16 + li * 2 + 0] = make_float4(m[s][0], m[s][1], m[s][2], m[s][3]);
        omp[s * 16 + li * 2 + 1] = make_float4(m[s][4], m[s][5], m[s][6], m[s][7]);
    }
    const size_t O_a    = (size_t)B * (S * D);
    const size_t O_g    = O_a + (size_t)B * S;
    const size_t O_mc   = O_g + (size_t)B * S;
    const size_t O_load = O_mc + (size_t)B * S;
    const size_t O_tot  = O_load + (size_t)B;
    const size_t O_ms   = O_tot + (size_t)B;

    out[O_a  + sidx] = a;
    out[O_g  + sidx] = gl;
    out[O_mc + sidx] = mc;
    if (li == 0) {
        out[O_load + b] = (float)mload;
        out[O_tot  + b] = tot;
        out[O_ms   + b] = msum * 0.125f;
    }
}

extern "C" void kernel_launch(void* const* d_in, const int* in_sizes, int n_in,
                              void* d_out, int out_size)
{
    const int B = in_sizes[0] / (S * D);
    const int threads = 128;
    const int total = B * 8;               // 8 lanes per batch
    const int blocks = (total + threads - 1) / threads;

    bwm_kernel<<<blocks, threads>>>(
        (const float*)d_in[0], (const float*)d_in[1], (const float*)d_in[2],
        (const float*)d_in[3], (const float*)d_in[4], (const float*)d_in[5],
        (const float*)d_in[6], (const float*)d_in[7], (const float*)d_in[8],
        (const float*)d_in[9],
        (const int*)(n_in > 10 ? d_in[10] : nullptr),
        (float*)d_out, B);
}

// round 6
// speedup vs baseline: 1.1175x; 1.1175x over previous
#include <cuda_runtime.h>
#include <cstdint>

#define FULL 0xffffffffu
#define S 8
#define D 64

typedef unsigned long long u64;

__device__ __forceinline__ float finf() { return __int_as_float(0x7f800000); }

__device__ __forceinline__ u64 pack2(float lo, float hi) {
    u64 r; asm("mov.b64 %0, {%1, %2};" : "=l"(r) : "f"(lo), "f"(hi)); return r;
}
__device__ __forceinline__ void unpack2(u64 v, float& lo, float& hi) {
    asm("mov.b64 {%0, %1}, %2;" : "=f"(lo), "=f"(hi) : "l"(v));
}
__device__ __forceinline__ u64 fma2(u64 a, u64 b, u64 c) {
    u64 d; asm("fma.rn.f32x2 %0, %1, %2, %3;" : "=l"(d) : "l"(a), "l"(b), "l"(c)); return d;
}
__device__ __forceinline__ u64 mul2(u64 a, u64 b) {
    u64 d; asm("mul.rn.f32x2 %0, %1, %2;" : "=l"(d) : "l"(a), "l"(b)); return d;
}

__global__ __launch_bounds__(128, 5)
void bwm_kernel(const float* __restrict__ g_m,     // B*S*D
                const float* __restrict__ g_act,   // B*S
                const float* __restrict__ g_gate,  // B*S
                const float* __restrict__ g_thr,   // B*S
                const float* __restrict__ g_rstr,  // B*S
                const float* __restrict__ g_W,     // B*S*S
                const float* __restrict__ g_mcur,  // B*S
                const float* __restrict__ g_inp,   // B*D
                const float* __restrict__ g_gsig,  // B*S
                const float* __restrict__ g_rsig,  // B*S
                const int*   __restrict__ g_dt,    // 1 elem (int or float bits) or null
                float* __restrict__ out,
                int B)
{
    const int tid  = blockIdx.x * blockDim.x + threadIdx.x;
    const int b    = tid >> 3;             // batch index (8 lanes per batch)
    const int lane = threadIdx.x & 31;
    const int li   = lane & 7;             // lane-in-group = slot id this lane owns
    const unsigned gsh = (lane >> 3) * 8;  // group bit-shift for ballots
    if (b >= B) return;                    // grid exact: B*8 % 128 == 0, no partial warps

    // ---- load m (each lane: 8 floats = 4 f32x2 of every slot), decay 0.95 ----
    const size_t bm = (size_t)b * (S * D);
    const ulonglong2* mp = (const ulonglong2*)(g_m + bm);
    const u64 K95 = pack2(0.95f, 0.95f);
    u64 m2[S][4];
#pragma unroll
    for (int s = 0; s < S; s++) {
        ulonglong2 u = mp[s * 16 + li * 2 + 0];
        ulonglong2 v = mp[s * 16 + li * 2 + 1];
        m2[s][0] = mul2(u.x, K95); m2[s][1] = mul2(u.y, K95);
        m2[s][2] = mul2(v.x, K95); m2[s][3] = mul2(v.y, K95);
    }

    // ---- early scalars: activities + W row (needed in interference loop) ----
    const int sidx = b * S + li;
    const float a0 = g_act[sidx];

    // W row, pre-scaled by 0.1 (lane li holds W[li][0..7]*0.1)
    const float4* wp = (const float4*)(g_W + (size_t)b * (S * S) + li * S);
    float4 w0 = wp[0], w1 = wp[1];
    float Wr[8] = {0.1f*w0.x, 0.1f*w0.y, 0.1f*w0.z, 0.1f*w0.w,
                   0.1f*w1.x, 0.1f*w1.y, 0.1f*w1.z, 0.1f*w1.w};

    // ---- decayed activity + activation mask ----
    float a = 0.9f * a0;
    unsigned actm = (__ballot_sync(FULL, a > 0.1f) >> gsh) & 0xFFu;

    // ---- target slot selection (uses ORIGINAL activities) ----
    bool avail = a0 < 0.2f;
    unsigned avm = (__ballot_sync(FULL, avail) >> gsh) & 0xFFu;
    float key = avm ? (avail ? a0 : finf()) : a0;
    float bv = key; int bi = li;
#pragma unroll
    for (int o = 1; o < 8; o <<= 1) {
        float ov = __shfl_xor_sync(FULL, bv, o);
        int   oi = __shfl_xor_sync(FULL, bi, o);
        if (ov < bv || (ov == bv && oi < bi)) { bv = ov; bi = oi; }
    }
    const int ts = bi;  // uniform within group

    // ---- initial squared norms of all 8 slots (replicated across lanes) ----
    float ns[S];
#pragma unroll
    for (int s = 0; s < S; s++) {
        u64 acc = 0;
#pragma unroll
        for (int t = 0; t < 4; t++) acc = fma2(m2[s][t], m2[s][t], acc);
        float lo, hi; unpack2(acc, lo, hi);
        ns[s] = lo + hi;
    }
#pragma unroll
    for (int o = 1; o < 8; o <<= 1) {
#pragma unroll
        for (int s = 0; s < S; s++) ns[s] += __shfl_xor_sync(FULL, ns[s], o);
    }

    // ---- sequential pairwise interference (exact order i=0..7, j=0..7, j!=i) ----
#pragma unroll
    for (int i = 0; i < S; i++) {
        const bool acti = (actm >> i) & 1u;
#pragma unroll
        for (int j = 0; j < S; j++) {
            if (j == i) continue;
            u64 acc = 0;
#pragma unroll
            for (int t = 0; t < 4; t++) acc = fma2(m2[i][t], m2[j][t], acc);
            float lo, hi; unpack2(acc, lo, hi);
            float dot = lo + hi;
            dot += __shfl_xor_sync(FULL, dot, 1);
            dot += __shfl_xor_sync(FULL, dot, 2);
            dot += __shfl_xor_sync(FULL, dot, 4);

            float denom = sqrtf(ns[i] * ns[j]) + 1e-6f;
            float sim = __fdividef(dot, denom);
            float Wij = __shfl_sync(FULL, Wr[j], i, 8);   // = W[i][j]*0.1
            bool cond = acti && ((actm >> j) & 1u);
            float sc = cond ? Wij * sim : 0.0f;
            u64 nsc = pack2(-sc, -sc);
#pragma unroll
            for (int t = 0; t < 4; t++) m2[i][t] = fma2(nsc, m2[j][t], m2[i][t]);
            // ||mi - sc*mj||^2 = ni - 2 sc dot + sc^2 nj (analytic norm update)
            ns[i] = fmaf(sc * sc, ns[j], fmaf(-2.0f * sc, dot, ns[i]));
        }
    }

    // ============ deferred loads (reduce register pressure in hot loop) ============
    const float gate = g_gate[sidx];
    const float gsig = g_gsig[sidx];
    const float thr  = g_thr[sidx];
    const float rstr = g_rstr[sidx];
    const float rsig = g_rsig[sidx];
    const float mcur = g_mcur[sidx];

    const ulonglong2* ip = (const ulonglong2*)(g_inp + (size_t)b * D);
    ulonglong2 iv0 = ip[li * 2 + 0];
    ulonglong2 iv1 = ip[li * 2 + 1];
    u64 inp2[4] = {iv0.x, iv0.y, iv1.x, iv1.y};

    // ---- gating / write ----
    float gl = fmaf(0.3f, fminf(fmaxf(gsig, 0.0f), 1.0f), 0.7f * gate);
    float gs = __shfl_sync(FULL, gl, ts, 8);
    float tv = __shfl_sync(FULL, thr, ts, 8);
    bool wr = gs > tv;

    // input norm (reduced over group)
    {
        u64 acc = 0;
#pragma unroll
        for (int t = 0; t < 4; t++) acc = fma2(inp2[t], inp2[t], acc);
        float lo, hi; unpack2(acc, lo, hi);
        float insq = lo + hi;
        insq += __shfl_xor_sync(FULL, insq, 1);
        insq += __shfl_xor_sync(FULL, insq, 2);
        insq += __shfl_xor_sync(FULL, insq, 4);
        if (wr && li == ts) a = sqrtf(insq);
    }

    // blend: m[ts] = (1-c)*m[ts] + c*inp, exact no-op for other slots (c=0)
    {
        const float c = wr ? gs * 0.3f : 0.0f;
        const u64 NEG1 = pack2(-1.0f, -1.0f);
#pragma unroll
        for (int s = 0; s < S; s++) {
            float cs = (s == ts) ? c : 0.0f;
            u64 c2 = pack2(cs, cs);
#pragma unroll
            for (int t = 0; t < 4; t++) {
                u64 d = fma2(m2[s][t], NEG1, inp2[t]);   // inp - m
                m2[s][t] = fma2(c2, d, m2[s][t]);        // m + cs*(inp-m)
            }
        }
    }

    // ---- refresh (activity part) ----
    float ru = fminf(fmaxf(rsig, 0.0f), 1.0f);
    float rs = (ru > 0.1f) ? rstr * ru : 0.0f;
    a += rs;

    // ---- maintenance current ----
    float dt = 1.0f;
    if (g_dt) {
        int ib = *g_dt;
        float f = __int_as_float(ib);
        dt = (fabsf(f) > 1e-30f && fabsf(f) < 1e30f) ? f : (float)ib;
    }
    float mc = (a > 0.1f) ? fmaf(fmaf(0.5f, a, -mcur), 0.1f * dt, mcur)
                          : mcur * 0.95f;

    // ---- capacity-based deactivation (activity part) ----
    bool active = a > 0.1f;
    unsigned ab = (__ballot_sync(FULL, active) >> gsh) & 0xFFu;
    int ndeact = max(__popc(ab) - 4, 0);
    float mv = active ? a : finf();
    int rank = 0;
#pragma unroll
    for (int s = 0; s < S; s++) {
        float vs = __shfl_sync(FULL, mv, s, 8);
        rank += (vs < mv || (vs == mv && s < li)) ? 1 : 0;
    }
    bool de = active && (rank < ndeact);
    if (de) a *= 0.5f;
    unsigned db = (__ballot_sync(FULL, de) >> gsh) & 0xFFu;

    // ---- fused m scaling: refresh*(1+rs_s) then deact*0.7 (multiplies commute) ----
#pragma unroll
    for (int s = 0; s < S; s++) {
        float f = 1.0f + __shfl_sync(FULL, rs, s, 8);
        if ((db >> s) & 1u) f *= 0.7f;
        u64 f2 = pack2(f, f);
#pragma unroll
        for (int t = 0; t < 4; t++) m2[s][t] = mul2(m2[s][t], f2);
    }

    // ---- scalar outputs ----
    unsigned lb = (__ballot_sync(FULL, a > 0.1f) >> gsh) & 0xFFu;
    int mload = __popc(lb);
    float tot = a, msum = mc;
#pragma unroll
    for (int o = 1; o < 8; o <<= 1) {
        tot  += __shfl_xor_sync(FULL, tot, o);
        msum += __shfl_xor_sync(FULL, msum, o);
    }

    // ---- stores ----
    ulonglong2* omp = (ulonglong2*)(out + bm);
#pragma unroll
    for (int s = 0; s < S; s++) {
        omp[s * 16 + li * 2 + 0] = make_ulonglong2(m2[s][0], m2[s][1]);
        omp[s * 16 + li * 2 + 1] = make_ulonglong2(m2[s][2], m2[s][3]);
    }
    const size_t O_a    = (size_t)B * (S * D);
    const size_t O_g    = O_a + (size_t)B * S;
    const size_t O_mc   = O_g + (size_t)B * S;
    const size_t O_load = O_mc + (size_t)B * S;
    const size_t O_tot  = O_load + (size_t)B;
    const size_t O_ms   = O_tot + (size_t)B;

    out[O_a  + sidx] = a;
    out[O_g  + sidx] = gl;
    out[O_mc + sidx] = mc;
    if (li == 0) {
        out[O_load + b] = (float)mload;
        out[O_tot  + b] = tot;
        out[O_ms   + b] = msum * 0.125f;
    }
}

extern "C" void kernel_launch(void* const* d_in, const int* in_sizes, int n_in,
                              void* d_out, int out_size)
{
    const int B = in_sizes[0] / (S * D);
    const int threads = 128;
    const int total = B * 8;               // 8 lanes per batch
    const int blocks = (total + threads - 1) / threads;

    bwm_kernel<<<blocks, threads>>>(
        (const float*)d_in[0], (const float*)d_in[1], (const float*)d_in[2],
        (const float*)d_in[3], (const float*)d_in[4], (const float*)d_in[5],
        (const float*)d_in[6], (const float*)d_in[7], (const float*)d_in[8],
        (const float*)d_in[9],
        (const int*)(n_in > 10 ? d_in[10] : nullptr),
        (float*)d_out, B);
}

// round 15
// speedup vs baseline: 1.4920x; 1.3351x over previous
#include <cuda_runtime.h>
#include <cstdint>

#define FULL 0xffffffffu
#define S 8
#define D 64

typedef unsigned long long u64;

__device__ __forceinline__ float finf() { return __int_as_float(0x7f800000); }

__device__ __forceinline__ u64 pack2(float lo, float hi) {
    u64 r; asm("mov.b64 %0, {%1, %2};" : "=l"(r) : "f"(lo), "f"(hi)); return r;
}
__device__ __forceinline__ void unpack2(u64 v, float& lo, float& hi) {
    asm("mov.b64 {%0, %1}, %2;" : "=f"(lo), "=f"(hi) : "l"(v));
}
__device__ __forceinline__ u64 fma2(u64 a, u64 b, u64 c) {
    u64 d; asm("fma.rn.f32x2 %0, %1, %2, %3;" : "=l"(d) : "l"(a), "l"(b), "l"(c)); return d;
}
__device__ __forceinline__ u64 mul2(u64 a, u64 b) {
    u64 d; asm("mul.rn.f32x2 %0, %1, %2;" : "=l"(d) : "l"(a), "l"(b)); return d;
}

// Symmetric Gram access: canonical storage in upper triangle (row-major).
// All indices are compile-time constants after full unroll -> pure registers.
#define GREF(a, b) Gm[((a) < (b)) ? ((a) * 8 + (b)) : ((b) * 8 + (a))]

__global__ __launch_bounds__(128, 4)
void bwm_kernel(const float* __restrict__ g_m,     // B*S*D
                const float* __restrict__ g_act,   // B*S
                const float* __restrict__ g_gate,  // B*S
                const float* __restrict__ g_thr,   // B*S
                const float* __restrict__ g_rstr,  // B*S
                const float* __restrict__ g_W,     // B*S*S
                const float* __restrict__ g_mcur,  // B*S
                const float* __restrict__ g_inp,   // B*D
                const float* __restrict__ g_gsig,  // B*S
                const float* __restrict__ g_rsig,  // B*S
                const int*   __restrict__ g_dt,    // 1 elem (int or float bits) or null
                float* __restrict__ out,
                int B)
{
    const int tid  = blockIdx.x * blockDim.x + threadIdx.x;
    const int b    = tid >> 3;             // batch index (8 lanes per batch)
    const int lane = threadIdx.x & 31;
    const int li   = lane & 7;             // lane-in-group = slot id this lane owns
    const unsigned gsh = (lane >> 3) * 8;  // group bit-shift for ballots
    if (b >= B) return;                    // grid exact: B*8 % 128 == 0, no partial warps

    // ---- load m (each lane: 8 floats = 4 f32x2 of every slot), decay 0.95 ----
    const size_t bm = (size_t)b * (S * D);
    const ulonglong2* mp = (const ulonglong2*)(g_m + bm);
    const u64 K95 = pack2(0.95f, 0.95f);
    u64 m2[S][4];
#pragma unroll
    for (int s = 0; s < S; s++) {
        ulonglong2 u = mp[s * 16 + li * 2 + 0];
        ulonglong2 v = mp[s * 16 + li * 2 + 1];
        m2[s][0] = mul2(u.x, K95); m2[s][1] = mul2(u.y, K95);
        m2[s][2] = mul2(v.x, K95); m2[s][3] = mul2(v.y, K95);
    }

    // ---- early scalars ----
    const int sidx = b * S + li;
    const float a0 = g_act[sidx];

    // W row, pre-scaled by 0.1 (lane li holds W[li][0..7]*0.1)
    const float4* wp = (const float4*)(g_W + (size_t)b * (S * S) + li * S);
    float4 w0 = wp[0], w1 = wp[1];
    float Wr[8] = {0.1f*w0.x, 0.1f*w0.y, 0.1f*w0.z, 0.1f*w0.w,
                   0.1f*w1.x, 0.1f*w1.y, 0.1f*w1.z, 0.1f*w1.w};

    // ---- decayed activity + activation mask ----
    float a = 0.9f * a0;
    unsigned actm = (__ballot_sync(FULL, a > 0.1f) >> gsh) & 0xFFu;

    // ---- target slot selection (uses ORIGINAL activities) ----
    bool avail = a0 < 0.2f;
    unsigned avm = (__ballot_sync(FULL, avail) >> gsh) & 0xFFu;
    float key = avm ? (avail ? a0 : finf()) : a0;
    float bv = key; int bi = li;
#pragma unroll
    for (int o = 1; o < 8; o <<= 1) {
        float ov = __shfl_xor_sync(FULL, bv, o);
        int   oi = __shfl_xor_sync(FULL, bi, o);
        if (ov < bv || (ov == bv && oi < bi)) { bv = ov; bi = oi; }
    }
    const int ts = bi;  // uniform within group

    // ---- build replicated Gram matrix: Gm[a][b] = m_a . m_b (upper tri + diag) ----
    float Gm[64];
#pragma unroll
    for (int aa = 0; aa < S; aa++) {
#pragma unroll
        for (int bb = aa; bb < S; bb++) {
            u64 acc = 0;
#pragma unroll
            for (int t = 0; t < 4; t++) acc = fma2(m2[aa][t], m2[bb][t], acc);
            float lo, hi; unpack2(acc, lo, hi);
            Gm[aa * 8 + bb] = lo + hi;
        }
    }
    // all-reduce the 36 partials across the 8 lanes (pipelined, off-chain)
#pragma unroll
    for (int o = 1; o < 8; o <<= 1) {
#pragma unroll
        for (int aa = 0; aa < S; aa++)
#pragma unroll
            for (int bb = aa; bb < S; bb++)
                Gm[aa * 8 + bb] += __shfl_xor_sync(FULL, Gm[aa * 8 + bb], o);
    }

    // ---- sequential pairwise interference via analytic Gram maintenance ----
    // Exact order i=0..7, j=0..7 (j!=i). All dots are register-local.
#pragma unroll
    for (int i = 0; i < S; i++) {
        const bool acti = (actm >> i) & 1u;
#pragma unroll
        for (int j = 0; j < S; j++) {
            if (j == i) continue;
            float dot = GREF(i, j);
            float nsi = GREF(i, i);
            float nsj = GREF(j, j);
            // 1/(sqrt(nsi*nsj)) ; +1e-6 eps in ref is ~1.6e-8 relative here (norms ~60)
            float inv = rsqrtf(fmaxf(nsi * nsj, 1e-12f));
            float Wij = __shfl_sync(FULL, Wr[j], i, 8);   // = W[i][j]*0.1, off-chain
            bool cond = acti && ((actm >> j) & 1u);
            float sc = cond ? (Wij * dot * inv) : 0.0f;

            // diag (analytic): ||mi - sc*mj||^2 = nsi - 2 sc dot + sc^2 nsj
            GREF(i, i) = fmaf(sc * sc, nsj, fmaf(-2.0f * sc, dot, nsi));
            // row i of G: G[i][k] -= sc * G[j][k]  (k != i; k=j uses nsj, correct)
#pragma unroll
            for (int k = 0; k < S; k++) {
                if (k == i) continue;
                GREF(i, k) = fmaf(-sc, GREF(j, k), GREF(i, k));
            }
            // vector update (off the scalar chain)
            u64 nsc = pack2(-sc, -sc);
#pragma unroll
            for (int t = 0; t < 4; t++) m2[i][t] = fma2(nsc, m2[j][t], m2[i][t]);
        }
    }

    // ============ deferred loads (reduce register pressure in hot loop) ============
    const float gate = g_gate[sidx];
    const float gsig = g_gsig[sidx];
    const float thr  = g_thr[sidx];
    const float rstr = g_rstr[sidx];
    const float rsig = g_rsig[sidx];
    const float mcur = g_mcur[sidx];

    const ulonglong2* ip = (const ulonglong2*)(g_inp + (size_t)b * D);
    ulonglong2 iv0 = ip[li * 2 + 0];
    ulonglong2 iv1 = ip[li * 2 + 1];
    u64 inp2[4] = {iv0.x, iv0.y, iv1.x, iv1.y};

    // ---- gating / write ----
    float gl = fmaf(0.3f, fminf(fmaxf(gsig, 0.0f), 1.0f), 0.7f * gate);
    float gs = __shfl_sync(FULL, gl, ts, 8);
    float tv = __shfl_sync(FULL, thr, ts, 8);
    bool wr = gs > tv;

    // input norm (reduced over group)
    {
        u64 acc = 0;
#pragma unroll
        for (int t = 0; t < 4; t++) acc = fma2(inp2[t], inp2[t], acc);
        float lo, hi; unpack2(acc, lo, hi);
        float insq = lo + hi;
        insq += __shfl_xor_sync(FULL, insq, 1);
        insq += __shfl_xor_sync(FULL, insq, 2);
        insq += __shfl_xor_sync(FULL, insq, 4);
        if (wr && li == ts) a = sqrtf(insq);
    }

    // blend: m[ts] = (1-c)*m[ts] + c*inp, exact no-op for other slots (c=0)
    {
        const float c = wr ? gs * 0.3f : 0.0f;
        const u64 NEG1 = pack2(-1.0f, -1.0f);
#pragma unroll
        for (int s = 0; s < S; s++) {
            float cs = (s == ts) ? c : 0.0f;
            u64 c2 = pack2(cs, cs);
#pragma unroll
            for (int t = 0; t < 4; t++) {
                u64 d = fma2(m2[s][t], NEG1, inp2[t]);   // inp - m
                m2[s][t] = fma2(c2, d, m2[s][t]);        // m + cs*(inp-m)
            }
        }
    }

    // ---- refresh (activity part) ----
    float ru = fminf(fmaxf(rsig, 0.0f), 1.0f);
    float rs = (ru > 0.1f) ? rstr * ru : 0.0f;
    a += rs;

    // ---- maintenance current ----
    float dt = 1.0f;
    if (g_dt) {
        int ib = *g_dt;
        float f = __int_as_float(ib);
        dt = (fabsf(f) > 1e-30f && fabsf(f) < 1e30f) ? f : (float)ib;
    }
    float mc = (a > 0.1f) ? fmaf(fmaf(0.5f, a, -mcur), 0.1f * dt, mcur)
                          : mcur * 0.95f;

    // ---- capacity-based deactivation (activity part) ----
    bool active = a > 0.1f;
    unsigned ab = (__ballot_sync(FULL, active) >> gsh) & 0xFFu;
    int ndeact = max(__popc(ab) - 4, 0);
    float mv = active ? a : finf();
    int rank = 0;
#pragma unroll
    for (int s = 0; s < S; s++) {
        float vs = __shfl_sync(FULL, mv, s, 8);
        rank += (vs < mv || (vs == mv && s < li)) ? 1 : 0;
    }
    bool de = active && (rank < ndeact);
    if (de) a *= 0.5f;
    unsigned db = (__ballot_sync(FULL, de) >> gsh) & 0xFFu;

    // ---- fused m scaling: refresh*(1+rs_s) then deact*0.7 (multiplies commute) ----
#pragma unroll
    for (int s = 0; s < S; s++) {
        float f = 1.0f + __shfl_sync(FULL, rs, s, 8);
        if ((db >> s) & 1u) f *= 0.7f;
        u64 f2 = pack2(f, f);
#pragma unroll
        for (int t = 0; t < 4; t++) m2[s][t] = mul2(m2[s][t], f2);
    }

    // ---- scalar outputs ----
    unsigned lb = (__ballot_sync(FULL, a > 0.1f) >> gsh) & 0xFFu;
    int mload = __popc(lb);
    float tot = a, msum = mc;
#pragma unroll
    for (int o = 1; o < 8; o <<= 1) {
        tot  += __shfl_xor_sync(FULL, tot, o);
        msum += __shfl_xor_sync(FULL, msum, o);
    }

    // ---- stores ----
    ulonglong2* omp = (ulonglong2*)(out + bm);
#pragma unroll
    for (int s = 0; s < S; s++) {
        omp[s * 16 + li * 2 + 0] = make_ulonglong2(m2[s][0], m2[s][1]);
        omp[s * 16 + li * 2 + 1] = make_ulonglong2(m2[s][2], m2[s][3]);
    }
    const size_t O_a    = (size_t)B * (S * D);
    const size_t O_g    = O_a + (size_t)B * S;
    const size_t O_mc   = O_g + (size_t)B * S;
    const size_t O_load = O_mc + (size_t)B * S;
    const size_t O_tot  = O_load + (size_t)B;
    const size_t O_ms   = O_tot + (size_t)B;

    out[O_a  + sidx] = a;
    out[O_g  + sidx] = gl;
    out[O_mc + sidx] = mc;
    if (li == 0) {
        out[O_load + b] = (float)mload;
        out[O_tot  + b] = tot;
        out[O_ms   + b] = msum * 0.125f;
    }
}

extern "C" void kernel_launch(void* const* d_in, const int* in_sizes, int n_in,
                              void* d_out, int out_size)
{
    const int B = in_sizes[0] / (S * D);
    const int threads = 128;
    const int total = B * 8;               // 8 lanes per batch
    const int blocks = (total + threads - 1) / threads;

    bwm_kernel<<<blocks, threads>>>(
        (const float*)d_in[0], (const float*)d_in[1], (const float*)d_in[2],
        (const float*)d_in[3], (const float*)d_in[4], (const float*)d_in[5],
        (const float*)d_in[6], (const float*)d_in[7], (const float*)d_in[8],
        (const float*)d_in[9],
        (const int*)(n_in > 10 ? d_in[10] : nullptr),
        (float*)d_out, B);
}